// round 10
// baseline (speedup 1.0000x reference)
#include <cuda_runtime.h>
#include <cuda_fp16.h>
#include <mma.h>
#include <cstdint>

using namespace nvcuda;

#define NN 20000
#define NE 640000
#define HC 256      // H * C = 4 * 64
#define NH 4
#define FULLM 0xffffffffu
#define NEGINF -3.4e38f

// ---------------- scratch (static device globals; no allocation) ----------
__device__ __align__(16) __half g_xh[NN * HC];    // MMA output (fp16, gathered in agg)
__device__ __align__(16) __half g_xin16[NN * HC]; // fp16 copy of layer input for MMA
__device__ __align__(16) __half g_w16[HC * HC];   // fp16 weights (current layer)
__device__ float g_agg[NN * HC];       // h between layers (fp32)
__device__ float g_asrc[NN * NH];
__device__ float g_adst[NN * NH];
__device__ float g_alpha_s[NE * NH];   // spill buffer for deg > 96 nodes only
__device__ float g_ce[2 * NH];
__device__ float g_pa[8 * HC];         // projected a-vectors: [0..3]=src, [4..7]=dst
// CSR
__device__ int g_deg[NN];
__device__ __align__(16) int g_rowstart[NN + 4];
__device__ int g_cursor[NN];
__device__ int g_esrc_s[NE];
__device__ int g_eid_s[NE];
__device__ __align__(8) float2 g_ea_s[NE];      // {eattr, atten} in CSR order

struct __align__(16) h8 { __half2 a, b, c, d; };

// ---------------- tiny setup kernels --------------------------------------
__global__ void k_ce(const float* __restrict__ We1, const float* __restrict__ ae1,
                     const float* __restrict__ We2, const float* __restrict__ ae2) {
    __shared__ float s1[256], s2[256];
    int t = threadIdx.x;
    s1[t] = We1[t] * ae1[t];
    s2[t] = We2[t] * ae2[t];
    __syncthreads();
    if (t < 8) {
        const float* s = (t >= 4) ? s2 : s1;
        int h = t & 3;
        float sum = 0.f;
#pragma unroll
        for (int c = 0; c < 64; c++) sum += s[h * 64 + c];
        g_ce[t] = sum;
    }
}

// W (K x 256) -> fp16
__global__ void k_cvtw(const float* __restrict__ W, int total) {
    int i = blockIdx.x * blockDim.x + threadIdx.x;
    if (i < total) g_w16[i] = __float2half_rn(W[i]);
}

// pa[h][k] = sum_c W[k][h*64+c]*a_src[h][c];  pa[4+h][k] same with a_dst
__global__ void k_pa(const float* __restrict__ W, const float* __restrict__ as,
                     const float* __restrict__ ad, int K) {
    __shared__ float sa[256], sd[256];
    int t = threadIdx.x;
    sa[t] = as[t]; sd[t] = ad[t];
    __syncthreads();
    if (t < K) {
        const float* wr = W + (size_t)t * HC;
#pragma unroll
        for (int h = 0; h < 4; h++) {
            float s = 0.f, d = 0.f;
#pragma unroll
            for (int c = 0; c < 64; c++) {
                float w = wr[h * 64 + c];
                s = fmaf(w, sa[h * 64 + c], s);
                d = fmaf(w, sd[h * 64 + c], d);
            }
            g_pa[h * HC + t] = s;
            g_pa[(4 + h) * HC + t] = d;
        }
    }
}

// ---------------- CSR build ------------------------------------------------
__global__ void k_zero_deg() {
    int i = blockIdx.x * blockDim.x + threadIdx.x;
    if (i < NN) g_deg[i] = 0;
}

__global__ void k_hist(const int* __restrict__ dst) {
    int e = blockIdx.x * blockDim.x + threadIdx.x;
    if (e < NE) atomicAdd(&g_deg[dst[e]], 1);
}

__global__ void k_scan() {
    extern __shared__ int sdeg[];
    __shared__ int wsum[32];
    int t = threadIdx.x;

    for (int i = t; i < NN / 4; i += 1024)
        ((int4*)sdeg)[i] = ((const int4*)g_deg)[i];
    __syncthreads();

    int loc[20];
    int tot = 0;
    if (t < 1000) {
        int base = t * 20;
#pragma unroll
        for (int i = 0; i < 20; i++) { loc[i] = tot; tot += sdeg[base + i]; }
    }
    int lane = t & 31, w = t >> 5;
    int v = tot;
#pragma unroll
    for (int o = 1; o < 32; o <<= 1) {
        int u = __shfl_up_sync(FULLM, v, o);
        if (lane >= o) v += u;
    }
    if (lane == 31) wsum[w] = v;
    __syncthreads();
    if (w == 0) {
        int s = wsum[lane];
#pragma unroll
        for (int o = 1; o < 32; o <<= 1) {
            int u = __shfl_up_sync(FULLM, s, o);
            if (lane >= o) s += u;
        }
        wsum[lane] = s;
    }
    __syncthreads();
    int excl = v - tot + (w ? wsum[w - 1] : 0);
    __syncthreads();
    if (t < 1000) {
        int base = t * 20;
#pragma unroll
        for (int i = 0; i < 20; i++) sdeg[base + i] = excl + loc[i];
    }
    __syncthreads();
    for (int i = t; i < NN / 4; i += 1024) {
        int4 r = ((const int4*)sdeg)[i];
        ((int4*)g_rowstart)[i] = r;
        ((int4*)g_cursor)[i] = r;
    }
    if (t == 0) g_rowstart[NN] = NE;
}

__global__ void k_scatter(const int* __restrict__ src, const int* __restrict__ dst,
                          const float* __restrict__ eattr, const float* __restrict__ atten) {
    int e = blockIdx.x * blockDim.x + threadIdx.x;
    if (e >= NE) return;
    int d = dst[e];
    int pos = atomicAdd(&g_cursor[d], 1);
    g_esrc_s[pos] = src[e];
    g_eid_s[pos] = e;
    g_ea_s[pos] = make_float2(eattr[e], atten[e]);
}

// ---------------- prep: X fp32 -> fp16 copy + exact fp32 logit projections -
// warp per row. pa_t padded [256][9] for conflict-free LDS.
__global__ void __launch_bounds__(256) k_prep(const float* __restrict__ X, int K) {
    __shared__ float pa_t[256][9];
    const float* Xp = X ? X : g_agg;
    int tid = threadIdx.x;
    for (int i = tid; i < 8 * K; i += 256) {
        int j = i / K, k = i - j * K;
        pa_t[k][j] = g_pa[j * HC + k];
    }
    __syncthreads();
    int wrp = tid >> 5, lane = tid & 31;
    int n = blockIdx.x * 8 + wrp;
    if (n >= NN) return;
    const float* xr = Xp + (size_t)n * K;
    __half* xo = g_xin16 + (size_t)n * K;
    float d0 = 0.f, d1 = 0.f, d2 = 0.f, d3 = 0.f;
    float d4 = 0.f, d5 = 0.f, d6 = 0.f, d7 = 0.f;
    for (int it = 0; it < K; it += 32) {
        int c = it + lane;
        float v = xr[c];
        xo[c] = __float2half_rn(v);
        d0 = fmaf(v, pa_t[c][0], d0); d1 = fmaf(v, pa_t[c][1], d1);
        d2 = fmaf(v, pa_t[c][2], d2); d3 = fmaf(v, pa_t[c][3], d3);
        d4 = fmaf(v, pa_t[c][4], d4); d5 = fmaf(v, pa_t[c][5], d5);
        d6 = fmaf(v, pa_t[c][6], d6); d7 = fmaf(v, pa_t[c][7], d7);
    }
#pragma unroll
    for (int o = 16; o; o >>= 1) {
        d0 += __shfl_xor_sync(FULLM, d0, o); d1 += __shfl_xor_sync(FULLM, d1, o);
        d2 += __shfl_xor_sync(FULLM, d2, o); d3 += __shfl_xor_sync(FULLM, d3, o);
        d4 += __shfl_xor_sync(FULLM, d4, o); d5 += __shfl_xor_sync(FULLM, d5, o);
        d6 += __shfl_xor_sync(FULLM, d6, o); d7 += __shfl_xor_sync(FULLM, d7, o);
    }
    if (lane < 4) {
        float v = (lane == 0) ? d0 : (lane == 1) ? d1 : (lane == 2) ? d2 : d3;
        g_asrc[n * NH + lane] = v;
    } else if (lane < 8) {
        float v = (lane == 4) ? d4 : (lane == 5) ? d5 : (lane == 6) ? d6 : d7;
        g_adst[n * NH + lane - 4] = v;
    }
}

// ---------------- tensor-core GEMM: g_xh = Xf16 @ Wf16 (fp32 acc) ----------
// grid (ceil(NN/128), 4); block 256 (8 warps); warp = 16 rows x 64 cols.
__global__ void __launch_bounds__(256) k_mma(int K) {
    __shared__ __align__(16) float cs[8][16 * 64];   // 32 KB
    int wrp = threadIdx.x >> 5, lane = threadIdx.x & 31;
    int row0 = blockIdx.x * 128 + wrp * 16;
    int col0 = blockIdx.y * 64;
    if (row0 >= NN) return;                    // NN % 16 == 0, no straddle

    wmma::fragment<wmma::accumulator, 16, 16, 16, float> acc[4];
#pragma unroll
    for (int j = 0; j < 4; j++) wmma::fill_fragment(acc[j], 0.f);

    const __half* A = g_xin16 + (size_t)row0 * K;
    for (int k = 0; k < K; k += 16) {
        wmma::fragment<wmma::matrix_a, 16, 16, 16, __half, wmma::row_major> a;
        wmma::load_matrix_sync(a, A + k, K);
#pragma unroll
        for (int j = 0; j < 4; j++) {
            wmma::fragment<wmma::matrix_b, 16, 16, 16, __half, wmma::row_major> b;
            wmma::load_matrix_sync(b, g_w16 + (size_t)k * HC + col0 + j * 16, HC);
            wmma::mma_sync(acc[j], a, b, acc[j]);
        }
    }
#pragma unroll
    for (int j = 0; j < 4; j++)
        wmma::store_matrix_sync(&cs[wrp][j * 16], acc[j], 64, wmma::mem_row_major);
    __syncwarp();

    int r = lane & 15, half_sel = lane >> 4;
    const float* sr = &cs[wrp][r * 64 + half_sel * 32];
    __half* dr = &g_xh[(size_t)(row0 + r) * HC + col0 + half_sel * 32];
#pragma unroll
    for (int i = 0; i < 4; i++) {
        float4 f0 = ((const float4*)sr)[i * 2];
        float4 f1 = ((const float4*)sr)[i * 2 + 1];
        h8 u;
        u.a = __floats2half2_rn(f0.x, f0.y);
        u.b = __floats2half2_rn(f0.z, f0.w);
        u.c = __floats2half2_rn(f1.x, f1.y);
        u.d = __floats2half2_rn(f1.z, f1.w);
        ((h8*)dr)[i] = u;
    }
}

__device__ __forceinline__ float lrelu(float v) { return v >= 0.f ? v : 0.2f * v; }

// ---------------- fused logits + softmax + aggregation ---------------------
__global__ void __launch_bounds__(256)
k_agg(const float* __restrict__ bias, int ce_off,
      float* __restrict__ wout, float* __restrict__ outp) {
    __shared__ float s_c[8][128];
    __shared__ int   s_s[8][32];
    int wrp = threadIdx.x >> 5;
    int n = blockIdx.x * 8 + wrp;
    int lane = threadIdx.x & 31;
    if (n >= NN) return;
    int r0 = g_rowstart[n], r1 = g_rowstart[n + 1];
    int deg = r1 - r0;
    int nchunk = (deg + 31) >> 5;
    float4 ad = *(const float4*)&g_adst[n * 4];
    float ce0 = g_ce[ce_off + 0], ce1 = g_ce[ce_off + 1];
    float ce2 = g_ce[ce_off + 2], ce3 = g_ce[ce_off + 3];

    float4 ra[3];
    int    rs[3], ro[3];
    float  rat[3];
    float m0 = NEGINF, m1 = NEGINF, m2 = NEGINF, m3 = NEGINF;
    float s0 = 0.f, s1 = 0.f, s2 = 0.f, s3 = 0.f;

#pragma unroll
    for (int c = 0; c < 3; c++) {
        ra[c] = make_float4(NEGINF, NEGINF, NEGINF, NEGINF);
        rs[c] = 0; ro[c] = 0; rat[c] = 0.f;
        if (c < nchunk) {
            int j = r0 + c * 32 + lane;
            if (j < r1) {
                int s = g_esrc_s[j];
                int orig = g_eid_s[j];
                float2 ea2 = g_ea_s[j];
                float4 as4 = *(const float4*)&g_asrc[s * 4];
                float4 a;
                a.x = lrelu(as4.x + ea2.x * ce0 + ad.x);
                a.y = lrelu(as4.y + ea2.x * ce1 + ad.y);
                a.z = lrelu(as4.z + ea2.x * ce2 + ad.z);
                a.w = lrelu(as4.w + ea2.x * ce3 + ad.w);
                ra[c] = a; rs[c] = s; ro[c] = orig; rat[c] = ea2.y;
                float t;
                t = fmaxf(m0, a.x); s0 = s0 * __expf(m0 - t) + __expf(a.x - t); m0 = t;
                t = fmaxf(m1, a.y); s1 = s1 * __expf(m1 - t) + __expf(a.y - t); m1 = t;
                t = fmaxf(m2, a.z); s2 = s2 * __expf(m2 - t) + __expf(a.z - t); m2 = t;
                t = fmaxf(m3, a.w); s3 = s3 * __expf(m3 - t) + __expf(a.w - t); m3 = t;
            }
        }
    }
    for (int c = 3; c < nchunk; c++) {
        int j = r0 + c * 32 + lane;
        if (j < r1) {
            int s = g_esrc_s[j];
            float2 ea2 = g_ea_s[j];
            float4 as4 = *(const float4*)&g_asrc[s * 4];
            float4 a;
            a.x = lrelu(as4.x + ea2.x * ce0 + ad.x);
            a.y = lrelu(as4.y + ea2.x * ce1 + ad.y);
            a.z = lrelu(as4.z + ea2.x * ce2 + ad.z);
            a.w = lrelu(as4.w + ea2.x * ce3 + ad.w);
            *(float4*)&g_alpha_s[(size_t)j * 4] = a;
            float t;
            t = fmaxf(m0, a.x); s0 = s0 * __expf(m0 - t) + __expf(a.x - t); m0 = t;
            t = fmaxf(m1, a.y); s1 = s1 * __expf(m1 - t) + __expf(a.y - t); m1 = t;
            t = fmaxf(m2, a.z); s2 = s2 * __expf(m2 - t) + __expf(a.z - t); m2 = t;
            t = fmaxf(m3, a.w); s3 = s3 * __expf(m3 - t) + __expf(a.w - t); m3 = t;
        }
    }
#pragma unroll
    for (int o = 16; o; o >>= 1) {
        float om, os, nm;
        om = __shfl_xor_sync(FULLM, m0, o); os = __shfl_xor_sync(FULLM, s0, o);
        nm = fmaxf(m0, om); s0 = s0 * __expf(m0 - nm) + os * __expf(om - nm); m0 = nm;
        om = __shfl_xor_sync(FULLM, m1, o); os = __shfl_xor_sync(FULLM, s1, o);
        nm = fmaxf(m1, om); s1 = s1 * __expf(m1 - nm) + os * __expf(om - nm); m1 = nm;
        om = __shfl_xor_sync(FULLM, m2, o); os = __shfl_xor_sync(FULLM, s2, o);
        nm = fmaxf(m2, om); s2 = s2 * __expf(m2 - nm) + os * __expf(om - nm); m2 = nm;
        om = __shfl_xor_sync(FULLM, m3, o); os = __shfl_xor_sync(FULLM, s3, o);
        nm = fmaxf(m3, om); s3 = s3 * __expf(m3 - nm) + os * __expf(om - nm); m3 = nm;
    }
    float i0 = 1.f / (s0 + 1e-16f), i1 = 1.f / (s1 + 1e-16f);
    float i2 = 1.f / (s2 + 1e-16f), i3 = 1.f / (s3 + 1e-16f);

    float acc0 = 0.f, acc1 = 0.f, acc2 = 0.f, acc3 = 0.f;
    float acc4 = 0.f, acc5 = 0.f, acc6 = 0.f, acc7 = 0.f;
    int h = lane >> 3;
    int c0 = lane * 8;

    for (int c = 0; c < nchunk; c++) {
        int base = r0 + c * 32;
        int j = base + lane;
        bool valid = j < r1;
        int cnt = min(32, r1 - base);
        float4 a; int s; float at; int orig;
        if (c < 3) {
            a = ra[c]; s = rs[c]; at = rat[c]; orig = ro[c];
        } else {
            s = valid ? g_esrc_s[j] : 0;
            orig = valid ? g_eid_s[j] : 0;
            float2 ea2 = valid ? g_ea_s[j] : make_float2(0.f, 0.f);
            a = valid ? *(const float4*)&g_alpha_s[(size_t)j * 4]
                      : make_float4(NEGINF, NEGINF, NEGINF, NEGINF);
            at = ea2.y;
        }
        float w0 = __expf(a.x - m0) * i0;
        float w1 = __expf(a.y - m1) * i1;
        float w2 = __expf(a.z - m2) * i2;
        float w3 = __expf(a.w - m3) * i3;
        if (valid)
            *(float4*)&wout[(size_t)orig * 4] = make_float4(w0, w1, w2, w3);
        __syncwarp();
        *(float4*)&s_c[wrp][lane * 4] = make_float4(w0 * at, w1 * at, w2 * at, w3 * at);
        s_s[wrp][lane] = s;
        __syncwarp();
        for (int k = 0; k < cnt; k++) {
            float coef = s_c[wrp][k * 4 + h];
            int ss = s_s[wrp][k];
            h8 v = *(const h8*)&g_xh[(size_t)ss * HC + c0];
            float2 f0 = __half22float2(v.a);
            float2 f1 = __half22float2(v.b);
            float2 f2 = __half22float2(v.c);
            float2 f3 = __half22float2(v.d);
            acc0 = fmaf(f0.x, coef, acc0); acc1 = fmaf(f0.y, coef, acc1);
            acc2 = fmaf(f1.x, coef, acc2); acc3 = fmaf(f1.y, coef, acc3);
            acc4 = fmaf(f2.x, coef, acc4); acc5 = fmaf(f2.y, coef, acc5);
            acc6 = fmaf(f3.x, coef, acc6); acc7 = fmaf(f3.y, coef, acc7);
        }
        __syncwarp();
    }

    float4 b0 = *(const float4*)&bias[c0];
    float4 b1 = *(const float4*)&bias[c0 + 4];
    float* op = outp ? &outp[(size_t)n * HC + c0] : &g_agg[(size_t)n * HC + c0];
    *(float4*)op = make_float4(acc0 + b0.x, acc1 + b0.y, acc2 + b0.z, acc3 + b0.w);
    *(float4*)(op + 4) = make_float4(acc4 + b1.x, acc5 + b1.y, acc6 + b1.z, acc7 + b1.w);
}

// ---------------- launch ---------------------------------------------------
extern "C" void kernel_launch(void* const* d_in, const int* in_sizes, int n_in,
                              void* d_out, int out_size) {
    const float* x       = (const float*)d_in[0];
    const int*   ei      = (const int*)d_in[1];
    const int*   src     = ei;
    const int*   dst     = ei + NE;
    const float* eattr   = (const float*)d_in[3];
    const float* eatten  = (const float*)d_in[4];
    const float* W1      = (const float*)d_in[5];
    const float* a_src1  = (const float*)d_in[6];
    const float* a_dst1  = (const float*)d_in[7];
    const float* W_e1    = (const float*)d_in[8];
    const float* a_e1    = (const float*)d_in[9];
    const float* b1      = (const float*)d_in[10];
    const float* W2      = (const float*)d_in[11];
    const float* a_src2  = (const float*)d_in[12];
    const float* a_dst2  = (const float*)d_in[13];
    const float* W_e2    = (const float*)d_in[14];
    const float* a_e2    = (const float*)d_in[15];
    const float* b2      = (const float*)d_in[16];

    float* out    = (float*)d_out;
    float* h_out  = out;                        // [NN, 256]
    float* w1_out = out + (size_t)NN * HC;      // [NE, 4]
    float* w2_out = w1_out + (size_t)NE * NH;   // [NE, 4]

    const int EB = (NE + 255) / 256;            // 2500
    const int NB = (NN + 255) / 256;            // 79
    const int AB = NN / 8;                      // 2500
    const int PB = NN / 8;                      // 2500 (warp per row)
    dim3 mma_grid((NN + 127) / 128, NH);

    cudaFuncSetAttribute(k_scan, cudaFuncAttributeMaxDynamicSharedMemorySize, NN * 4);

    k_ce<<<1, 256>>>(W_e1, a_e1, W_e2, a_e2);

    // ---- CSR build (shared by both layers) ----
    k_zero_deg<<<NB, 256>>>();
    k_hist<<<EB, 256>>>(dst);
    k_scan<<<1, 1024, NN * 4>>>();
    k_scatter<<<EB, 256>>>(src, dst, eattr, eatten);

    // ---- layer 1 ----
    k_pa<<<1, 256>>>(W1, a_src1, a_dst1, 128);
    k_cvtw<<<(128 * 256 + 255) / 256, 256>>>(W1, 128 * 256);
    k_prep<<<PB, 256>>>(x, 128);
    k_mma<<<mma_grid, 256>>>(128);
    k_agg<<<AB, 256>>>(b1, 0, w1_out, nullptr);   // -> g_agg

    // ---- layer 2 ----
    k_pa<<<1, 256>>>(W2, a_src2, a_dst2, 256);
    k_cvtw<<<(256 * 256 + 255) / 256, 256>>>(W2, 256 * 256);
    k_prep<<<PB, 256>>>(nullptr /*g_agg*/, 256);
    k_mma<<<mma_grid, 256>>>(256);
    k_agg<<<AB, 256>>>(b2, 4, w2_out, h_out);
}

// round 11
// speedup vs baseline: 2.0417x; 2.0417x over previous
#include <cuda_runtime.h>
#include <cuda_fp16.h>
#include <cstdint>

#define NN 20000
#define NE 640000
#define HC 256      // H * C = 4 * 64
#define NH 4
#define FULLM 0xffffffffu
#define NEGINF -3.4e38f
#define NSB 79      // scan blocks: ceil(NN/256)

// ---------------- scratch (static device globals; no allocation) ----------
__device__ __align__(16) __half g_xh[NN * HC];  // per-layer features (fp16 for gather BW)
__device__ float g_agg[NN * HC];       // h between layers (fp32)
__device__ float g_asrc[NN * NH];
__device__ float g_adst[NN * NH];
__device__ float g_alpha_s[NE * NH];   // spill buffer for deg > 96 nodes only
__device__ float g_ce[2 * NH];
// CSR
__device__ int g_deg[NN];
__device__ __align__(16) int g_rowstart[NN + 4];
__device__ int g_cursor[NN];
__device__ int g_esrc_s[NE];
__device__ int g_eid_s[NE];
__device__ __align__(8) float2 g_ea_s[NE];      // {eattr, atten} in CSR order
__device__ int g_bsum[NSB + 1];

struct __align__(16) h8 { __half2 a, b, c, d; };

// ---------------- tiny setup kernels --------------------------------------
__global__ void k_ce(const float* __restrict__ We1, const float* __restrict__ ae1,
                     const float* __restrict__ We2, const float* __restrict__ ae2) {
    __shared__ float s1[256], s2[256];
    int t = threadIdx.x;
    s1[t] = We1[t] * ae1[t];
    s2[t] = We2[t] * ae2[t];
    __syncthreads();
    if (t < 8) {
        const float* s = (t >= 4) ? s2 : s1;
        int h = t & 3;
        float sum = 0.f;
#pragma unroll
        for (int c = 0; c < 64; c++) sum += s[h * 64 + c];
        g_ce[t] = sum;
    }
}

// ---------------- CSR build ------------------------------------------------
__global__ void k_zero_deg() {
    int i = blockIdx.x * blockDim.x + threadIdx.x;
    if (i < NN) g_deg[i] = 0;
}

__global__ void k_hist(const int* __restrict__ dst) {
    int e = blockIdx.x * blockDim.x + threadIdx.x;
    if (e < NE) atomicAdd(&g_deg[dst[e]], 1);
}

// 3-phase multi-block exclusive scan of g_deg.
// A: per-block local exclusive scan (256 elems), local prefix -> g_rowstart, total -> g_bsum
__global__ void k_scanA() {
    __shared__ int ws[8];
    int t = threadIdx.x;
    int i = blockIdx.x * 256 + t;
    int v = (i < NN) ? g_deg[i] : 0;
    int lane = t & 31, w = t >> 5;
    int inc = v;
#pragma unroll
    for (int o = 1; o < 32; o <<= 1) {
        int u = __shfl_up_sync(FULLM, inc, o);
        if (lane >= o) inc += u;
    }
    if (lane == 31) ws[w] = inc;
    __syncthreads();
    if (w == 0 && lane < 8) {
        int s = ws[lane];
#pragma unroll
        for (int o = 1; o < 8; o <<= 1) {
            int u = __shfl_up_sync(0xffu, s, o);
            if (lane >= o) s += u;
        }
        ws[lane] = s;
        if (lane == 7) g_bsum[blockIdx.x] = s;
    }
    __syncthreads();
    int excl = inc - v + (w ? ws[w - 1] : 0);
    if (i < NN) g_rowstart[i] = excl;   // local prefix, fixed up in phase C
}

// B: tiny single-block scan of NSB block sums (exclusive)
__global__ void k_scanB() {
    int t = threadIdx.x;   // 128 threads
    __shared__ int s[NSB];
    if (t < NSB) s[t] = g_bsum[t];
    __syncthreads();
    if (t == 0) {
        int run = 0;
#pragma unroll 4
        for (int i = 0; i < NSB; i++) { int v = s[i]; s[i] = run; run += v; }
    }
    __syncthreads();
    if (t < NSB) g_bsum[t] = s[t];
}

// C: add block offsets, write rowstart + cursor
__global__ void k_scanC() {
    int i = blockIdx.x * 256 + threadIdx.x;
    if (i < NN) {
        int r = g_rowstart[i] + g_bsum[blockIdx.x];
        g_rowstart[i] = r;
        g_cursor[i] = r;
    }
    if (i == 0) g_rowstart[NN] = NE;
}

__global__ void k_scatter(const int* __restrict__ src, const int* __restrict__ dst,
                          const float* __restrict__ eattr, const float* __restrict__ atten) {
    int e = blockIdx.x * blockDim.x + threadIdx.x;
    if (e >= NE) return;
    int d = dst[e];
    int pos = atomicAdd(&g_cursor[d], 1);
    g_esrc_s[pos] = src[e];
    g_eid_s[pos] = e;
    g_ea_s[pos] = make_float2(eattr[e], atten[e]);
}

// ---------------- GEMM: xh = X @ W (fp16 out), fused alpha_src/alpha_dst ---
__global__ void __launch_bounds__(128)
k_gemm(const float* __restrict__ X, const float* __restrict__ W,
       const float* __restrict__ a_src, const float* __restrict__ a_dst, int K) {
    __shared__ __align__(16) float As[16][132];
    __shared__ __align__(16) float Bs[16][68];
    const float* Xp = X ? X : g_agg;

    int tid = threadIdx.x;
    int tx = tid & 7, ty = tid >> 3;
    int r0 = blockIdx.x * 128;
    int head = blockIdx.y;
    int c0 = head * 64;

    float acc[8][8] = {};

    for (int kk = 0; kk < K; kk += 16) {
#pragma unroll
        for (int l = 0; l < 4; l++) {
            int i = tid + 128 * l;
            int row = i >> 2;
            int kq = i & 3;
            float4 v = make_float4(0.f, 0.f, 0.f, 0.f);
            int gr = r0 + row;
            if (gr < NN) v = *(const float4*)&Xp[(size_t)gr * K + kk + kq * 4];
            As[kq * 4 + 0][row] = v.x;
            As[kq * 4 + 1][row] = v.y;
            As[kq * 4 + 2][row] = v.z;
            As[kq * 4 + 3][row] = v.w;
        }
#pragma unroll
        for (int l = 0; l < 2; l++) {
            int i = tid + 128 * l;
            int kr = i >> 4;
            int cq = i & 15;
            float4 v = *(const float4*)&W[(size_t)(kk + kr) * HC + c0 + cq * 4];
            *(float4*)&Bs[kr][cq * 4] = v;
        }
        __syncthreads();
#pragma unroll
        for (int k = 0; k < 16; k++) {
            float4 a0 = *(float4*)&As[k][ty * 4];
            float4 a1 = *(float4*)&As[k][64 + ty * 4];
            float4 b0 = *(float4*)&Bs[k][tx * 4];
            float4 b1 = *(float4*)&Bs[k][32 + tx * 4];
            float ar[8] = {a0.x, a0.y, a0.z, a0.w, a1.x, a1.y, a1.z, a1.w};
            float br[8] = {b0.x, b0.y, b0.z, b0.w, b1.x, b1.y, b1.z, b1.w};
#pragma unroll
            for (int i = 0; i < 8; i++)
#pragma unroll
                for (int j = 0; j < 8; j++)
                    acc[i][j] = fmaf(ar[i], br[j], acc[i][j]);
        }
        __syncthreads();
    }

    float4 as0 = *(const float4*)&a_src[head * 64 + tx * 4];
    float4 as1 = *(const float4*)&a_src[head * 64 + 32 + tx * 4];
    float4 ad0 = *(const float4*)&a_dst[head * 64 + tx * 4];
    float4 ad1 = *(const float4*)&a_dst[head * 64 + 32 + tx * 4];
    float asv[8] = {as0.x, as0.y, as0.z, as0.w, as1.x, as1.y, as1.z, as1.w};
    float adv[8] = {ad0.x, ad0.y, ad0.z, ad0.w, ad1.x, ad1.y, ad1.z, ad1.w};

#pragma unroll
    for (int i = 0; i < 8; i++) {
        int gr = r0 + ((i < 4) ? (ty * 4 + i) : (64 + ty * 4 + i - 4));
        float ps = 0.f, pd = 0.f;
#pragma unroll
        for (int j = 0; j < 8; j++) {
            ps = fmaf(acc[i][j], asv[j], ps);
            pd = fmaf(acc[i][j], adv[j], pd);
        }
#pragma unroll
        for (int o = 4; o; o >>= 1) {
            ps += __shfl_down_sync(FULLM, ps, o, 8);
            pd += __shfl_down_sync(FULLM, pd, o, 8);
        }
        if (gr < NN) {
            __half2 h01 = __floats2half2_rn(acc[i][0], acc[i][1]);
            __half2 h23 = __floats2half2_rn(acc[i][2], acc[i][3]);
            __half2 h45 = __floats2half2_rn(acc[i][4], acc[i][5]);
            __half2 h67 = __floats2half2_rn(acc[i][6], acc[i][7]);
            __half2* xp = (__half2*)&g_xh[(size_t)gr * HC + c0];
            xp[tx * 2 + 0] = h01;
            xp[tx * 2 + 1] = h23;
            xp[16 + tx * 2 + 0] = h45;
            xp[16 + tx * 2 + 1] = h67;
            if (tx == 0) {
                g_asrc[gr * NH + head] = ps;
                g_adst[gr * NH + head] = pd;
            }
        }
    }
}

__device__ __forceinline__ float lrelu(float v) { return v >= 0.f ? v : 0.2f * v; }

// ---------------- fused logits + softmax + aggregation ---------------------
__global__ void __launch_bounds__(256)
k_agg(const float* __restrict__ bias, int ce_off,
      float* __restrict__ wout, float* __restrict__ outp) {
    __shared__ float s_c[8][128];
    __shared__ int   s_s[8][32];
    int wrp = threadIdx.x >> 5;
    int n = blockIdx.x * 8 + wrp;
    int lane = threadIdx.x & 31;
    if (n >= NN) return;
    int r0 = g_rowstart[n], r1 = g_rowstart[n + 1];
    int deg = r1 - r0;
    int nchunk = (deg + 31) >> 5;
    float4 ad = *(const float4*)&g_adst[n * 4];
    float ce0 = g_ce[ce_off + 0], ce1 = g_ce[ce_off + 1];
    float ce2 = g_ce[ce_off + 2], ce3 = g_ce[ce_off + 3];

    // ---- phase 1: inline logits + online (max, expsum) ----
    float4 ra[3];
    int    rs[3], ro[3];
    float  rat[3];
    float m0 = NEGINF, m1 = NEGINF, m2 = NEGINF, m3 = NEGINF;
    float s0 = 0.f, s1 = 0.f, s2 = 0.f, s3 = 0.f;

#pragma unroll
    for (int c = 0; c < 3; c++) {
        ra[c] = make_float4(NEGINF, NEGINF, NEGINF, NEGINF);
        rs[c] = 0; ro[c] = 0; rat[c] = 0.f;
        if (c < nchunk) {
            int j = r0 + c * 32 + lane;
            if (j < r1) {
                int s = g_esrc_s[j];
                int orig = g_eid_s[j];
                float2 ea2 = g_ea_s[j];
                float4 as4 = *(const float4*)&g_asrc[s * 4];
                float4 a;
                a.x = lrelu(as4.x + ea2.x * ce0 + ad.x);
                a.y = lrelu(as4.y + ea2.x * ce1 + ad.y);
                a.z = lrelu(as4.z + ea2.x * ce2 + ad.z);
                a.w = lrelu(as4.w + ea2.x * ce3 + ad.w);
                ra[c] = a; rs[c] = s; ro[c] = orig; rat[c] = ea2.y;
                float t;
                t = fmaxf(m0, a.x); s0 = s0 * __expf(m0 - t) + __expf(a.x - t); m0 = t;
                t = fmaxf(m1, a.y); s1 = s1 * __expf(m1 - t) + __expf(a.y - t); m1 = t;
                t = fmaxf(m2, a.z); s2 = s2 * __expf(m2 - t) + __expf(a.z - t); m2 = t;
                t = fmaxf(m3, a.w); s3 = s3 * __expf(m3 - t) + __expf(a.w - t); m3 = t;
            }
        }
    }
    for (int c = 3; c < nchunk; c++) {          // rare spill path (deg > 96)
        int j = r0 + c * 32 + lane;
        if (j < r1) {
            int s = g_esrc_s[j];
            float2 ea2 = g_ea_s[j];
            float4 as4 = *(const float4*)&g_asrc[s * 4];
            float4 a;
            a.x = lrelu(as4.x + ea2.x * ce0 + ad.x);
            a.y = lrelu(as4.y + ea2.x * ce1 + ad.y);
            a.z = lrelu(as4.z + ea2.x * ce2 + ad.z);
            a.w = lrelu(as4.w + ea2.x * ce3 + ad.w);
            *(float4*)&g_alpha_s[(size_t)j * 4] = a;
            float t;
            t = fmaxf(m0, a.x); s0 = s0 * __expf(m0 - t) + __expf(a.x - t); m0 = t;
            t = fmaxf(m1, a.y); s1 = s1 * __expf(m1 - t) + __expf(a.y - t); m1 = t;
            t = fmaxf(m2, a.z); s2 = s2 * __expf(m2 - t) + __expf(a.z - t); m2 = t;
            t = fmaxf(m3, a.w); s3 = s3 * __expf(m3 - t) + __expf(a.w - t); m3 = t;
        }
    }
#pragma unroll
    for (int o = 16; o; o >>= 1) {
        float om, os, nm;
        om = __shfl_xor_sync(FULLM, m0, o); os = __shfl_xor_sync(FULLM, s0, o);
        nm = fmaxf(m0, om); s0 = s0 * __expf(m0 - nm) + os * __expf(om - nm); m0 = nm;
        om = __shfl_xor_sync(FULLM, m1, o); os = __shfl_xor_sync(FULLM, s1, o);
        nm = fmaxf(m1, om); s1 = s1 * __expf(m1 - nm) + os * __expf(om - nm); m1 = nm;
        om = __shfl_xor_sync(FULLM, m2, o); os = __shfl_xor_sync(FULLM, s2, o);
        nm = fmaxf(m2, om); s2 = s2 * __expf(m2 - nm) + os * __expf(om - nm); m2 = nm;
        om = __shfl_xor_sync(FULLM, m3, o); os = __shfl_xor_sync(FULLM, s3, o);
        nm = fmaxf(m3, om); s3 = s3 * __expf(m3 - nm) + os * __expf(om - nm); m3 = nm;
    }
    float i0 = 1.f / (s0 + 1e-16f), i1 = 1.f / (s1 + 1e-16f);
    float i2 = 1.f / (s2 + 1e-16f), i3 = 1.f / (s3 + 1e-16f);

    // ---- phase 2: wout scatter + fp16 gather-accumulate ----
    float acc0 = 0.f, acc1 = 0.f, acc2 = 0.f, acc3 = 0.f;
    float acc4 = 0.f, acc5 = 0.f, acc6 = 0.f, acc7 = 0.f;
    int h = lane >> 3;
    int c0 = lane * 8;

    for (int c = 0; c < nchunk; c++) {
        int base = r0 + c * 32;
        int j = base + lane;
        bool valid = j < r1;
        int cnt = min(32, r1 - base);
        float4 a; int s; float at; int orig;
        if (c < 3) {
            a = ra[c]; s = rs[c]; at = rat[c]; orig = ro[c];
        } else {
            s = valid ? g_esrc_s[j] : 0;
            orig = valid ? g_eid_s[j] : 0;
            float2 ea2 = valid ? g_ea_s[j] : make_float2(0.f, 0.f);
            a = valid ? *(const float4*)&g_alpha_s[(size_t)j * 4]
                      : make_float4(NEGINF, NEGINF, NEGINF, NEGINF);
            at = ea2.y;
        }
        float w0 = __expf(a.x - m0) * i0;
        float w1 = __expf(a.y - m1) * i1;
        float w2 = __expf(a.z - m2) * i2;
        float w3 = __expf(a.w - m3) * i3;
        if (valid)
            *(float4*)&wout[(size_t)orig * 4] = make_float4(w0, w1, w2, w3);
        __syncwarp();
        *(float4*)&s_c[wrp][lane * 4] = make_float4(w0 * at, w1 * at, w2 * at, w3 * at);
        s_s[wrp][lane] = s;
        __syncwarp();
        if (cnt == 32) {
#pragma unroll 8
            for (int k = 0; k < 32; k++) {
                float coef = s_c[wrp][k * 4 + h];
                int ss = s_s[wrp][k];
                h8 v = *(const h8*)&g_xh[(size_t)ss * HC + c0];
                float2 f0 = __half22float2(v.a);
                float2 f1 = __half22float2(v.b);
                float2 f2 = __half22float2(v.c);
                float2 f3 = __half22float2(v.d);
                acc0 = fmaf(f0.x, coef, acc0); acc1 = fmaf(f0.y, coef, acc1);
                acc2 = fmaf(f1.x, coef, acc2); acc3 = fmaf(f1.y, coef, acc3);
                acc4 = fmaf(f2.x, coef, acc4); acc5 = fmaf(f2.y, coef, acc5);
                acc6 = fmaf(f3.x, coef, acc6); acc7 = fmaf(f3.y, coef, acc7);
            }
        } else {
            for (int k = 0; k < cnt; k++) {
                float coef = s_c[wrp][k * 4 + h];
                int ss = s_s[wrp][k];
                h8 v = *(const h8*)&g_xh[(size_t)ss * HC + c0];
                float2 f0 = __half22float2(v.a);
                float2 f1 = __half22float2(v.b);
                float2 f2 = __half22float2(v.c);
                float2 f3 = __half22float2(v.d);
                acc0 = fmaf(f0.x, coef, acc0); acc1 = fmaf(f0.y, coef, acc1);
                acc2 = fmaf(f1.x, coef, acc2); acc3 = fmaf(f1.y, coef, acc3);
                acc4 = fmaf(f2.x, coef, acc4); acc5 = fmaf(f2.y, coef, acc5);
                acc6 = fmaf(f3.x, coef, acc6); acc7 = fmaf(f3.y, coef, acc7);
            }
        }
        __syncwarp();
    }

    float4 b0 = *(const float4*)&bias[c0];
    float4 b1 = *(const float4*)&bias[c0 + 4];
    float* op = outp ? &outp[(size_t)n * HC + c0] : &g_agg[(size_t)n * HC + c0];
    *(float4*)op = make_float4(acc0 + b0.x, acc1 + b0.y, acc2 + b0.z, acc3 + b0.w);
    *(float4*)(op + 4) = make_float4(acc4 + b1.x, acc5 + b1.y, acc6 + b1.z, acc7 + b1.w);
}

// ---------------- launch ---------------------------------------------------
extern "C" void kernel_launch(void* const* d_in, const int* in_sizes, int n_in,
                              void* d_out, int out_size) {
    const float* x       = (const float*)d_in[0];
    const int*   ei      = (const int*)d_in[1];
    const int*   src     = ei;
    const int*   dst     = ei + NE;
    const float* eattr   = (const float*)d_in[3];
    const float* eatten  = (const float*)d_in[4];
    const float* W1      = (const float*)d_in[5];
    const float* a_src1  = (const float*)d_in[6];
    const float* a_dst1  = (const float*)d_in[7];
    const float* W_e1    = (const float*)d_in[8];
    const float* a_e1    = (const float*)d_in[9];
    const float* b1      = (const float*)d_in[10];
    const float* W2      = (const float*)d_in[11];
    const float* a_src2  = (const float*)d_in[12];
    const float* a_dst2  = (const float*)d_in[13];
    const float* W_e2    = (const float*)d_in[14];
    const float* a_e2    = (const float*)d_in[15];
    const float* b2      = (const float*)d_in[16];

    float* out    = (float*)d_out;
    float* h_out  = out;                        // [NN, 256]
    float* w1_out = out + (size_t)NN * HC;      // [NE, 4]
    float* w2_out = w1_out + (size_t)NE * NH;   // [NE, 4]

    const int EB = (NE + 255) / 256;            // 2500
    const int NB = (NN + 255) / 256;            // 79
    const int AB = NN / 8;                      // 2500
    dim3 gemm_grid((NN + 127) / 128, NH);

    k_ce<<<1, 256>>>(W_e1, a_e1, W_e2, a_e2);

    // ---- CSR build (shared by both layers) ----
    k_zero_deg<<<NB, 256>>>();
    k_hist<<<EB, 256>>>(dst);
    k_scanA<<<NSB, 256>>>();
    k_scanB<<<1, 128>>>();
    k_scanC<<<NSB, 256>>>();
    k_scatter<<<EB, 256>>>(src, dst, eattr, eatten);

    // ---- layer 1 ----
    k_gemm<<<gemm_grid, 128>>>(x, W1, a_src1, a_dst1, 128);
    k_agg<<<AB, 256>>>(b1, 0, w1_out, nullptr);   // -> g_agg

    // ---- layer 2 ----
    k_gemm<<<gemm_grid, 128>>>(nullptr /*g_agg*/, W2, a_src2, a_dst2, 256);
    k_agg<<<AB, 256>>>(b2, 4, w2_out, h_out);
}

// round 15
// speedup vs baseline: 2.1217x; 1.0391x over previous
#include <cuda_runtime.h>
#include <cuda_fp16.h>
#include <cstdint>

#define NN 20000
#define NE 640000
#define HC 256      // H * C = 4 * 64
#define NH 4
#define FULLM 0xffffffffu
#define NEGINF -3.4e38f
#define NSB 79      // scan blocks: ceil(NN/256)

// ---------------- scratch (static device globals; no allocation) ----------
__device__ __align__(16) __half g_xh[NN * HC];  // per-layer features (fp16 for gather BW)
__device__ float g_agg[NN * HC];       // h between layers (fp32)
__device__ float g_asrc[NN * NH];
__device__ float g_adst[NN * NH];
__device__ float g_alpha_s[NE * NH];   // spill buffer for deg > 96 nodes only
__device__ float g_ce[2 * NH];
// CSR
__device__ int g_deg[NN];
__device__ __align__(16) int g_rowstart[NN + 4];
__device__ int g_cursor[NN];
__device__ int g_esrc_s[NE];
__device__ int g_eid_s[NE];
__device__ __align__(8) float2 g_ea_s[NE];      // {eattr, atten} in CSR order
__device__ int g_bsum[NSB + 1];

struct __align__(16) h8 { __half2 a, b, c, d; };

// ---------------- tiny setup kernels --------------------------------------
__global__ void k_ce(const float* __restrict__ We1, const float* __restrict__ ae1,
                     const float* __restrict__ We2, const float* __restrict__ ae2) {
    __shared__ float s1[256], s2[256];
    int t = threadIdx.x;
    s1[t] = We1[t] * ae1[t];
    s2[t] = We2[t] * ae2[t];
    __syncthreads();
    if (t < 8) {
        const float* s = (t >= 4) ? s2 : s1;
        int h = t & 3;
        float sum = 0.f;
#pragma unroll
        for (int c = 0; c < 64; c++) sum += s[h * 64 + c];
        g_ce[t] = sum;
    }
}

// ---------------- CSR build ------------------------------------------------
__global__ void k_zero_deg() {
    int i = blockIdx.x * blockDim.x + threadIdx.x;
    if (i < NN) g_deg[i] = 0;
}

__global__ void k_hist(const int* __restrict__ dst) {
    int e = blockIdx.x * blockDim.x + threadIdx.x;
    if (e < NE) atomicAdd(&g_deg[dst[e]], 1);
}

// 3-phase multi-block exclusive scan of g_deg.
__global__ void k_scanA() {
    __shared__ int ws[8];
    int t = threadIdx.x;
    int i = blockIdx.x * 256 + t;
    int v = (i < NN) ? g_deg[i] : 0;
    int lane = t & 31, w = t >> 5;
    int inc = v;
#pragma unroll
    for (int o = 1; o < 32; o <<= 1) {
        int u = __shfl_up_sync(FULLM, inc, o);
        if (lane >= o) inc += u;
    }
    if (lane == 31) ws[w] = inc;
    __syncthreads();
    if (w == 0 && lane < 8) {
        int s = ws[lane];
#pragma unroll
        for (int o = 1; o < 8; o <<= 1) {
            int u = __shfl_up_sync(0xffu, s, o);
            if (lane >= o) s += u;
        }
        ws[lane] = s;
        if (lane == 7) g_bsum[blockIdx.x] = s;
    }
    __syncthreads();
    int excl = inc - v + (w ? ws[w - 1] : 0);
    if (i < NN) g_rowstart[i] = excl;   // local prefix, fixed up in phase C
}

__global__ void k_scanB() {
    int t = threadIdx.x;   // 128 threads
    __shared__ int s[NSB];
    if (t < NSB) s[t] = g_bsum[t];
    __syncthreads();
    if (t == 0) {
        int run = 0;
#pragma unroll 4
        for (int i = 0; i < NSB; i++) { int v = s[i]; s[i] = run; run += v; }
    }
    __syncthreads();
    if (t < NSB) g_bsum[t] = s[t];
}

__global__ void k_scanC() {
    int i = blockIdx.x * 256 + threadIdx.x;
    if (i < NN) {
        int r = g_rowstart[i] + g_bsum[blockIdx.x];
        g_rowstart[i] = r;
        g_cursor[i] = r;
    }
    if (i == 0) g_rowstart[NN] = NE;
}

__global__ void k_scatter(const int* __restrict__ src, const int* __restrict__ dst,
                          const float* __restrict__ eattr, const float* __restrict__ atten) {
    int e = blockIdx.x * blockDim.x + threadIdx.x;
    if (e >= NE) return;
    int d = dst[e];
    int pos = atomicAdd(&g_cursor[d], 1);
    g_esrc_s[pos] = src[e];
    g_eid_s[pos] = e;
    g_ea_s[pos] = make_float2(eattr[e], atten[e]);
}

// ---------------- GEMM: xh = X @ W (fp16 out), fused alpha_src/alpha_dst ---
__global__ void __launch_bounds__(128)
k_gemm(const float* __restrict__ X, const float* __restrict__ W,
       const float* __restrict__ a_src, const float* __restrict__ a_dst, int K) {
    __shared__ __align__(16) float As[16][132];
    __shared__ __align__(16) float Bs[16][68];
    const float* Xp = X ? X : g_agg;

    int tid = threadIdx.x;
    int tx = tid & 7, ty = tid >> 3;
    int r0 = blockIdx.x * 128;
    int head = blockIdx.y;
    int c0 = head * 64;

    float acc[8][8] = {};

    for (int kk = 0; kk < K; kk += 16) {
#pragma unroll
        for (int l = 0; l < 4; l++) {
            int i = tid + 128 * l;
            int row = i >> 2;
            int kq = i & 3;
            float4 v = make_float4(0.f, 0.f, 0.f, 0.f);
            int gr = r0 + row;
            if (gr < NN) v = *(const float4*)&Xp[(size_t)gr * K + kk + kq * 4];
            As[kq * 4 + 0][row] = v.x;
            As[kq * 4 + 1][row] = v.y;
            As[kq * 4 + 2][row] = v.z;
            As[kq * 4 + 3][row] = v.w;
        }
#pragma unroll
        for (int l = 0; l < 2; l++) {
            int i = tid + 128 * l;
            int kr = i >> 4;
            int cq = i & 15;
            float4 v = *(const float4*)&W[(size_t)(kk + kr) * HC + c0 + cq * 4];
            *(float4*)&Bs[kr][cq * 4] = v;
        }
        __syncthreads();
#pragma unroll
        for (int k = 0; k < 16; k++) {
            float4 a0 = *(float4*)&As[k][ty * 4];
            float4 a1 = *(float4*)&As[k][64 + ty * 4];
            float4 b0 = *(float4*)&Bs[k][tx * 4];
            float4 b1 = *(float4*)&Bs[k][32 + tx * 4];
            float ar[8] = {a0.x, a0.y, a0.z, a0.w, a1.x, a1.y, a1.z, a1.w};
            float br[8] = {b0.x, b0.y, b0.z, b0.w, b1.x, b1.y, b1.z, b1.w};
#pragma unroll
            for (int i = 0; i < 8; i++)
#pragma unroll
                for (int j = 0; j < 8; j++)
                    acc[i][j] = fmaf(ar[i], br[j], acc[i][j]);
        }
        __syncthreads();
    }

    float4 as0 = *(const float4*)&a_src[head * 64 + tx * 4];
    float4 as1 = *(const float4*)&a_src[head * 64 + 32 + tx * 4];
    float4 ad0 = *(const float4*)&a_dst[head * 64 + tx * 4];
    float4 ad1 = *(const float4*)&a_dst[head * 64 + 32 + tx * 4];
    float asv[8] = {as0.x, as0.y, as0.z, as0.w, as1.x, as1.y, as1.z, as1.w};
    float adv[8] = {ad0.x, ad0.y, ad0.z, ad0.w, ad1.x, ad1.y, ad1.z, ad1.w};

#pragma unroll
    for (int i = 0; i < 8; i++) {
        int gr = r0 + ((i < 4) ? (ty * 4 + i) : (64 + ty * 4 + i - 4));
        float ps = 0.f, pd = 0.f;
#pragma unroll
        for (int j = 0; j < 8; j++) {
            ps = fmaf(acc[i][j], asv[j], ps);
            pd = fmaf(acc[i][j], adv[j], pd);
        }
#pragma unroll
        for (int o = 4; o; o >>= 1) {
            ps += __shfl_down_sync(FULLM, ps, o, 8);
            pd += __shfl_down_sync(FULLM, pd, o, 8);
        }
        if (gr < NN) {
            __half2 h01 = __floats2half2_rn(acc[i][0], acc[i][1]);
            __half2 h23 = __floats2half2_rn(acc[i][2], acc[i][3]);
            __half2 h45 = __floats2half2_rn(acc[i][4], acc[i][5]);
            __half2 h67 = __floats2half2_rn(acc[i][6], acc[i][7]);
            __half2* xp = (__half2*)&g_xh[(size_t)gr * HC + c0];
            xp[tx * 2 + 0] = h01;
            xp[tx * 2 + 1] = h23;
            xp[16 + tx * 2 + 0] = h45;
            xp[16 + tx * 2 + 1] = h67;
            if (tx == 0) {
                g_asrc[gr * NH + head] = ps;
                g_adst[gr * NH + head] = pd;
            }
        }
    }
}

__device__ __forceinline__ float lrelu(float v) { return v >= 0.f ? v : 0.2f * v; }

// ---------------- fused logits + softmax + aggregation ---------------------
__global__ void __launch_bounds__(256)
k_agg(const float* __restrict__ bias, int ce_off,
      float* __restrict__ wout, float* __restrict__ outp) {
    __shared__ float s_c[8][128];
    __shared__ int   s_s[8][32];
    int wrp = threadIdx.x >> 5;
    int n = blockIdx.x * 8 + wrp;
    int lane = threadIdx.x & 31;
    if (n >= NN) return;
    int r0 = g_rowstart[n], r1 = g_rowstart[n + 1];
    int deg = r1 - r0;
    int nchunk = (deg + 31) >> 5;
    float4 ad = *(const float4*)&g_adst[n * 4];
    float ce0 = g_ce[ce_off + 0], ce1 = g_ce[ce_off + 1];
    float ce2 = g_ce[ce_off + 2], ce3 = g_ce[ce_off + 3];

    // ---- phase 1: inline logits + online (max, expsum) ----
    float4 ra[3];
    int    rs[3], ro[3];
    float  rat[3];
    float m0 = NEGINF, m1 = NEGINF, m2 = NEGINF, m3 = NEGINF;
    float s0 = 0.f, s1 = 0.f, s2 = 0.f, s3 = 0.f;

#pragma unroll
    for (int c = 0; c < 3; c++) {
        ra[c] = make_float4(NEGINF, NEGINF, NEGINF, NEGINF);
        rs[c] = 0; ro[c] = 0; rat[c] = 0.f;
        if (c < nchunk) {
            int j = r0 + c * 32 + lane;
            if (j < r1) {
                int s = g_esrc_s[j];
                int orig = g_eid_s[j];
                float2 ea2 = g_ea_s[j];
                float4 as4 = *(const float4*)&g_asrc[s * 4];
                float4 a;
                a.x = lrelu(as4.x + ea2.x * ce0 + ad.x);
                a.y = lrelu(as4.y + ea2.x * ce1 + ad.y);
                a.z = lrelu(as4.z + ea2.x * ce2 + ad.z);
                a.w = lrelu(as4.w + ea2.x * ce3 + ad.w);
                ra[c] = a; rs[c] = s; ro[c] = orig; rat[c] = ea2.y;
                float t;
                t = fmaxf(m0, a.x); s0 = s0 * __expf(m0 - t) + __expf(a.x - t); m0 = t;
                t = fmaxf(m1, a.y); s1 = s1 * __expf(m1 - t) + __expf(a.y - t); m1 = t;
                t = fmaxf(m2, a.z); s2 = s2 * __expf(m2 - t) + __expf(a.z - t); m2 = t;
                t = fmaxf(m3, a.w); s3 = s3 * __expf(m3 - t) + __expf(a.w - t); m3 = t;
            }
        }
    }
    for (int c = 3; c < nchunk; c++) {          // rare spill path (deg > 96)
        int j = r0 + c * 32 + lane;
        if (j < r1) {
            int s = g_esrc_s[j];
            float2 ea2 = g_ea_s[j];
            float4 as4 = *(const float4*)&g_asrc[s * 4];
            float4 a;
            a.x = lrelu(as4.x + ea2.x * ce0 + ad.x);
            a.y = lrelu(as4.y + ea2.x * ce1 + ad.y);
            a.z = lrelu(as4.z + ea2.x * ce2 + ad.z);
            a.w = lrelu(as4.w + ea2.x * ce3 + ad.w);
            *(float4*)&g_alpha_s[(size_t)j * 4] = a;
            float t;
            t = fmaxf(m0, a.x); s0 = s0 * __expf(m0 - t) + __expf(a.x - t); m0 = t;
            t = fmaxf(m1, a.y); s1 = s1 * __expf(m1 - t) + __expf(a.y - t); m1 = t;
            t = fmaxf(m2, a.z); s2 = s2 * __expf(m2 - t) + __expf(a.z - t); m2 = t;
            t = fmaxf(m3, a.w); s3 = s3 * __expf(m3 - t) + __expf(a.w - t); m3 = t;
        }
    }
#pragma unroll
    for (int o = 16; o; o >>= 1) {
        float om, os, nm;
        om = __shfl_xor_sync(FULLM, m0, o); os = __shfl_xor_sync(FULLM, s0, o);
        nm = fmaxf(m0, om); s0 = s0 * __expf(m0 - nm) + os * __expf(om - nm); m0 = nm;
        om = __shfl_xor_sync(FULLM, m1, o); os = __shfl_xor_sync(FULLM, s1, o);
        nm = fmaxf(m1, om); s1 = s1 * __expf(m1 - nm) + os * __expf(om - nm); m1 = nm;
        om = __shfl_xor_sync(FULLM, m2, o); os = __shfl_xor_sync(FULLM, s2, o);
        nm = fmaxf(m2, om); s2 = s2 * __expf(m2 - nm) + os * __expf(om - nm); m2 = nm;
        om = __shfl_xor_sync(FULLM, m3, o); os = __shfl_xor_sync(FULLM, s3, o);
        nm = fmaxf(m3, om); s3 = s3 * __expf(m3 - nm) + os * __expf(om - nm); m3 = nm;
    }
    float i0 = 1.f / (s0 + 1e-16f), i1 = 1.f / (s1 + 1e-16f);
    float i2 = 1.f / (s2 + 1e-16f), i3 = 1.f / (s3 + 1e-16f);

    // ---- phase 2: wout scatter + fp16 gather-accumulate ----
    float acc0 = 0.f, acc1 = 0.f, acc2 = 0.f, acc3 = 0.f;
    float acc4 = 0.f, acc5 = 0.f, acc6 = 0.f, acc7 = 0.f;
    int h = lane >> 3;
    int c0 = lane * 8;

    for (int c = 0; c < nchunk; c++) {
        int base = r0 + c * 32;
        int j = base + lane;
        bool valid = j < r1;
        int cnt = min(32, r1 - base);
        float4 a; int s; float at; int orig;
        if (c < 3) {
            a = ra[c]; s = rs[c]; at = rat[c]; orig = ro[c];
        } else {
            s = valid ? g_esrc_s[j] : 0;
            orig = valid ? g_eid_s[j] : 0;
            float2 ea2 = valid ? g_ea_s[j] : make_float2(0.f, 0.f);
            a = valid ? *(const float4*)&g_alpha_s[(size_t)j * 4]
                      : make_float4(NEGINF, NEGINF, NEGINF, NEGINF);
            at = ea2.y;
        }
        float w0 = __expf(a.x - m0) * i0;
        float w1 = __expf(a.y - m1) * i1;
        float w2 = __expf(a.z - m2) * i2;
        float w3 = __expf(a.w - m3) * i3;
        if (valid)
            *(float4*)&wout[(size_t)orig * 4] = make_float4(w0, w1, w2, w3);
        __syncwarp();
        *(float4*)&s_c[wrp][lane * 4] = make_float4(w0 * at, w1 * at, w2 * at, w3 * at);
        s_s[wrp][lane] = s;
        __syncwarp();
        for (int k = 0; k < cnt; k++) {
            float coef = s_c[wrp][k * 4 + h];
            int ss = s_s[wrp][k];
            h8 v = *(const h8*)&g_xh[(size_t)ss * HC + c0];
            float2 f0 = __half22float2(v.a);
            float2 f1 = __half22float2(v.b);
            float2 f2 = __half22float2(v.c);
            float2 f3 = __half22float2(v.d);
            acc0 = fmaf(f0.x, coef, acc0); acc1 = fmaf(f0.y, coef, acc1);
            acc2 = fmaf(f1.x, coef, acc2); acc3 = fmaf(f1.y, coef, acc3);
            acc4 = fmaf(f2.x, coef, acc4); acc5 = fmaf(f2.y, coef, acc5);
            acc6 = fmaf(f3.x, coef, acc6); acc7 = fmaf(f3.y, coef, acc7);
        }
        __syncwarp();
    }

    float4 b0 = *(const float4*)&bias[c0];
    float4 b1 = *(const float4*)&bias[c0 + 4];
    float* op = outp ? &outp[(size_t)n * HC + c0] : &g_agg[(size_t)n * HC + c0];
    *(float4*)op = make_float4(acc0 + b0.x, acc1 + b0.y, acc2 + b0.z, acc3 + b0.w);
    *(float4*)(op + 4) = make_float4(acc4 + b1.x, acc5 + b1.y, acc6 + b1.z, acc7 + b1.w);
}

// ---------------- launch ---------------------------------------------------
extern "C" void kernel_launch(void* const* d_in, const int* in_sizes, int n_in,
                              void* d_out, int out_size) {
    const float* x       = (const float*)d_in[0];
    const int*   ei      = (const int*)d_in[1];
    const int*   src     = ei;
    const int*   dst     = ei + NE;
    const float* eattr   = (const float*)d_in[3];
    const float* eatten  = (const float*)d_in[4];
    const float* W1      = (const float*)d_in[5];
    const float* a_src1  = (const float*)d_in[6];
    const float* a_dst1  = (const float*)d_in[7];
    const float* W_e1    = (const float*)d_in[8];
    const float* a_e1    = (const float*)d_in[9];
    const float* b1      = (const float*)d_in[10];
    const float* W2      = (const float*)d_in[11];
    const float* a_src2  = (const float*)d_in[12];
    const float* a_dst2  = (const float*)d_in[13];
    const float* W_e2    = (const float*)d_in[14];
    const float* a_e2    = (const float*)d_in[15];
    const float* b2      = (const float*)d_in[16];

    float* out    = (float*)d_out;
    float* h_out  = out;                        // [NN, 256]
    float* w1_out = out + (size_t)NN * HC;      // [NE, 4]
    float* w2_out = w1_out + (size_t)NE * NH;   // [NE, 4]

    const int EB = (NE + 255) / 256;            // 2500
    const int NB = (NN + 255) / 256;            // 79
    const int AB = NN / 8;                      // 2500
    dim3 gemm_grid((NN + 127) / 128, NH);

    k_ce<<<1, 256>>>(W_e1, a_e1, W_e2, a_e2);

    // ---- CSR build (shared by both layers) ----
    k_zero_deg<<<NB, 256>>>();
    k_hist<<<EB, 256>>>(dst);
    k_scanA<<<NSB, 256>>>();
    k_scanB<<<1, 128>>>();
    k_scanC<<<NSB, 256>>>();
    k_scatter<<<EB, 256>>>(src, dst, eattr, eatten);

    // ---- layer 1 ----
    k_gemm<<<gemm_grid, 128>>>(x, W1, a_src1, a_dst1, 128);
    k_agg<<<AB, 256>>>(b1, 0, w1_out, nullptr);   // -> g_agg

    // ---- layer 2 ----
    k_gemm<<<gemm_grid, 128>>>(nullptr /*g_agg*/, W2, a_src2, a_dst2, 256);
    k_agg<<<AB, 256>>>(b2, 4, w2_out, h_out);
}

// round 16
// speedup vs baseline: 2.4006x; 1.1315x over previous
#include <cuda_runtime.h>
#include <cuda_fp16.h>
#include <mma.h>
#include <cstdint>

using namespace nvcuda;

#define NN 20000
#define NE 640000
#define HC 256      // H * C = 4 * 64
#define NH 4
#define FULLM 0xffffffffu
#define NEGINF -3.4e38f
#define NSB 79      // scan blocks: ceil(NN/256)

// ---------------- scratch (static device globals; no allocation) ----------
__device__ __align__(16) __half g_xh[NN * HC];   // per-layer features (fp16)
__device__ __align__(16) __half g_h16[NN * HC];  // layer-1 output h1 in fp16 (MMA A)
__device__ __align__(16) __half g_w16[HC * HC];  // W2 in fp16 (MMA B)
__device__ float g_asrc[NN * NH];
__device__ float g_adst[NN * NH];
__device__ float g_alpha_s[NE * NH];   // spill buffer for deg > 96 nodes only
__device__ float g_ce[2 * NH];
// CSR
__device__ int g_deg[NN];
__device__ __align__(16) int g_rowstart[NN + 4];
__device__ int g_cursor[NN];
__device__ int g_esrc_s[NE];
__device__ int g_eid_s[NE];
__device__ __align__(8) float2 g_ea_s[NE];      // {eattr, atten} in CSR order
__device__ int g_bsum[NSB + 1];

struct __align__(16) h8 { __half2 a, b, c, d; };

// ---------------- tiny setup kernels --------------------------------------
__global__ void k_ce(const float* __restrict__ We1, const float* __restrict__ ae1,
                     const float* __restrict__ We2, const float* __restrict__ ae2) {
    __shared__ float s1[256], s2[256];
    int t = threadIdx.x;
    s1[t] = We1[t] * ae1[t];
    s2[t] = We2[t] * ae2[t];
    __syncthreads();
    if (t < 8) {
        const float* s = (t >= 4) ? s2 : s1;
        int h = t & 3;
        float sum = 0.f;
#pragma unroll
        for (int c = 0; c < 64; c++) sum += s[h * 64 + c];
        g_ce[t] = sum;
    }
}

// W2 (256 x 256) -> fp16
__global__ void k_cvtw(const float* __restrict__ W) {
    int i = blockIdx.x * blockDim.x + threadIdx.x;   // HC*HC/4 threads
    float4 v = ((const float4*)W)[i];
    h8* o = (h8*)&g_w16[0];
    __half2 a = __floats2half2_rn(v.x, v.y);
    __half2 b = __floats2half2_rn(v.z, v.w);
    ((__half2*)o)[i * 2 + 0] = a;
    ((__half2*)o)[i * 2 + 1] = b;
}

// ---------------- CSR build ------------------------------------------------
__global__ void k_zero_deg() {
    int i = blockIdx.x * blockDim.x + threadIdx.x;
    if (i < NN) g_deg[i] = 0;
}

__global__ void k_hist(const int* __restrict__ dst) {
    int e = blockIdx.x * blockDim.x + threadIdx.x;
    if (e < NE) atomicAdd(&g_deg[dst[e]], 1);
}

__global__ void k_scanA() {
    __shared__ int ws[8];
    int t = threadIdx.x;
    int i = blockIdx.x * 256 + t;
    int v = (i < NN) ? g_deg[i] : 0;
    int lane = t & 31, w = t >> 5;
    int inc = v;
#pragma unroll
    for (int o = 1; o < 32; o <<= 1) {
        int u = __shfl_up_sync(FULLM, inc, o);
        if (lane >= o) inc += u;
    }
    if (lane == 31) ws[w] = inc;
    __syncthreads();
    if (w == 0 && lane < 8) {
        int s = ws[lane];
#pragma unroll
        for (int o = 1; o < 8; o <<= 1) {
            int u = __shfl_up_sync(0xffu, s, o);
            if (lane >= o) s += u;
        }
        ws[lane] = s;
        if (lane == 7) g_bsum[blockIdx.x] = s;
    }
    __syncthreads();
    int excl = inc - v + (w ? ws[w - 1] : 0);
    if (i < NN) g_rowstart[i] = excl;
}

__global__ void k_scanB() {
    int t = threadIdx.x;
    __shared__ int s[NSB];
    if (t < NSB) s[t] = g_bsum[t];
    __syncthreads();
    if (t == 0) {
        int run = 0;
#pragma unroll 4
        for (int i = 0; i < NSB; i++) { int v = s[i]; s[i] = run; run += v; }
    }
    __syncthreads();
    if (t < NSB) g_bsum[t] = s[t];
}

__global__ void k_scanC() {
    int i = blockIdx.x * 256 + threadIdx.x;
    if (i < NN) {
        int r = g_rowstart[i] + g_bsum[blockIdx.x];
        g_rowstart[i] = r;
        g_cursor[i] = r;
    }
    if (i == 0) g_rowstart[NN] = NE;
}

__global__ void k_scatter(const int* __restrict__ src, const int* __restrict__ dst,
                          const float* __restrict__ eattr, const float* __restrict__ atten) {
    int e = blockIdx.x * blockDim.x + threadIdx.x;
    if (e >= NE) return;
    int d = dst[e];
    int pos = atomicAdd(&g_cursor[d], 1);
    g_esrc_s[pos] = src[e];
    g_eid_s[pos] = e;
    g_ea_s[pos] = make_float2(eattr[e], atten[e]);
}

// ---------------- layer-1 GEMM (fp32): xh = X @ W1, exact fused logits -----
__global__ void __launch_bounds__(128)
k_gemm(const float* __restrict__ X, const float* __restrict__ W,
       const float* __restrict__ a_src, const float* __restrict__ a_dst, int K) {
    __shared__ __align__(16) float As[16][132];
    __shared__ __align__(16) float Bs[16][68];

    int tid = threadIdx.x;
    int tx = tid & 7, ty = tid >> 3;
    int r0 = blockIdx.x * 128;
    int head = blockIdx.y;
    int c0 = head * 64;

    float acc[8][8] = {};

    for (int kk = 0; kk < K; kk += 16) {
#pragma unroll
        for (int l = 0; l < 4; l++) {
            int i = tid + 128 * l;
            int row = i >> 2;
            int kq = i & 3;
            float4 v = make_float4(0.f, 0.f, 0.f, 0.f);
            int gr = r0 + row;
            if (gr < NN) v = *(const float4*)&X[(size_t)gr * K + kk + kq * 4];
            As[kq * 4 + 0][row] = v.x;
            As[kq * 4 + 1][row] = v.y;
            As[kq * 4 + 2][row] = v.z;
            As[kq * 4 + 3][row] = v.w;
        }
#pragma unroll
        for (int l = 0; l < 2; l++) {
            int i = tid + 128 * l;
            int kr = i >> 4;
            int cq = i & 15;
            float4 v = *(const float4*)&W[(size_t)(kk + kr) * HC + c0 + cq * 4];
            *(float4*)&Bs[kr][cq * 4] = v;
        }
        __syncthreads();
#pragma unroll
        for (int k = 0; k < 16; k++) {
            float4 a0 = *(float4*)&As[k][ty * 4];
            float4 a1 = *(float4*)&As[k][64 + ty * 4];
            float4 b0 = *(float4*)&Bs[k][tx * 4];
            float4 b1 = *(float4*)&Bs[k][32 + tx * 4];
            float ar[8] = {a0.x, a0.y, a0.z, a0.w, a1.x, a1.y, a1.z, a1.w};
            float br[8] = {b0.x, b0.y, b0.z, b0.w, b1.x, b1.y, b1.z, b1.w};
#pragma unroll
            for (int i = 0; i < 8; i++)
#pragma unroll
                for (int j = 0; j < 8; j++)
                    acc[i][j] = fmaf(ar[i], br[j], acc[i][j]);
        }
        __syncthreads();
    }

    float4 as0 = *(const float4*)&a_src[head * 64 + tx * 4];
    float4 as1 = *(const float4*)&a_src[head * 64 + 32 + tx * 4];
    float4 ad0 = *(const float4*)&a_dst[head * 64 + tx * 4];
    float4 ad1 = *(const float4*)&a_dst[head * 64 + 32 + tx * 4];
    float asv[8] = {as0.x, as0.y, as0.z, as0.w, as1.x, as1.y, as1.z, as1.w};
    float adv[8] = {ad0.x, ad0.y, ad0.z, ad0.w, ad1.x, ad1.y, ad1.z, ad1.w};

#pragma unroll
    for (int i = 0; i < 8; i++) {
        int gr = r0 + ((i < 4) ? (ty * 4 + i) : (64 + ty * 4 + i - 4));
        float ps = 0.f, pd = 0.f;
#pragma unroll
        for (int j = 0; j < 8; j++) {
            ps = fmaf(acc[i][j], asv[j], ps);
            pd = fmaf(acc[i][j], adv[j], pd);
        }
#pragma unroll
        for (int o = 4; o; o >>= 1) {
            ps += __shfl_down_sync(FULLM, ps, o, 8);
            pd += __shfl_down_sync(FULLM, pd, o, 8);
        }
        if (gr < NN) {
            __half2 h01 = __floats2half2_rn(acc[i][0], acc[i][1]);
            __half2 h23 = __floats2half2_rn(acc[i][2], acc[i][3]);
            __half2 h45 = __floats2half2_rn(acc[i][4], acc[i][5]);
            __half2 h67 = __floats2half2_rn(acc[i][6], acc[i][7]);
            __half2* xp = (__half2*)&g_xh[(size_t)gr * HC + c0];
            xp[tx * 2 + 0] = h01;
            xp[tx * 2 + 1] = h23;
            xp[16 + tx * 2 + 0] = h45;
            xp[16 + tx * 2 + 1] = h67;
            if (tx == 0) {
                g_asrc[gr * NH + head] = ps;
                g_adst[gr * NH + head] = pd;
            }
        }
    }
}

// ---------------- layer-2 GEMM (HMMA): g_xh = h1f16 @ W2f16, fused logits --
// grid (ceil(NN/128), 2); block 256 = 8 warps (2 in M x 4 in N), warp 64x32.
// Dynamic smem: tiles A[128][32]h + B[32][128]h (16KB) unioned with
// Csm[128][132]f (67.6KB) for the epilogue.
__global__ void __launch_bounds__(256)
k_mma2(const float* __restrict__ a_src, const float* __restrict__ a_dst) {
    extern __shared__ char smem_raw[];
    __half* As = (__half*)smem_raw;                        // [128][32]
    __half* Bs = (__half*)(smem_raw + 128 * 32 * 2);       // [32][128]
    float*  Csm = (float*)smem_raw;                        // [128][132]

    int tid = threadIdx.x;
    int wid = tid >> 5;
    int wm = wid & 1;        // warp row (0/1): 64 M-rows each
    int wn = wid >> 1;       // warp col (0..3): 32 N-cols each
    int r0 = blockIdx.x * 128;
    int c0 = blockIdx.y * 128;

    wmma::fragment<wmma::accumulator, 16, 16, 16, float> acc[4][2];
#pragma unroll
    for (int i = 0; i < 4; i++)
#pragma unroll
        for (int j = 0; j < 2; j++) wmma::fill_fragment(acc[i][j], 0.f);

    for (int kk = 0; kk < HC; kk += 32) {
        // A tile: 128 rows x 32 cols fp16; 512 uint4, 2 per thread
#pragma unroll
        for (int l = 0; l < 2; l++) {
            int idx = tid + 256 * l;
            int row = idx >> 2, q = idx & 3;
            int gr = r0 + row;
            uint4 v = make_uint4(0u, 0u, 0u, 0u);
            if (gr < NN) v = *(const uint4*)&g_h16[(size_t)gr * HC + kk + q * 8];
            *(uint4*)&As[row * 32 + q * 8] = v;
        }
        // B tile: 32 rows x 128 cols fp16; 512 uint4, 2 per thread
#pragma unroll
        for (int l = 0; l < 2; l++) {
            int idx = tid + 256 * l;
            int kr = idx >> 4, q = idx & 15;
            *(uint4*)&Bs[kr * 128 + q * 8] =
                *(const uint4*)&g_w16[(size_t)(kk + kr) * HC + c0 + q * 8];
        }
        __syncthreads();
#pragma unroll
        for (int ks = 0; ks < 2; ks++) {
            wmma::fragment<wmma::matrix_a, 16, 16, 16, __half, wmma::row_major> af[4];
#pragma unroll
            for (int i = 0; i < 4; i++)
                wmma::load_matrix_sync(af[i], As + (wm * 64 + i * 16) * 32 + ks * 16, 32);
#pragma unroll
            for (int j = 0; j < 2; j++) {
                wmma::fragment<wmma::matrix_b, 16, 16, 16, __half, wmma::row_major> bf;
                wmma::load_matrix_sync(bf, Bs + (ks * 16) * 128 + wn * 32 + j * 16, 128);
#pragma unroll
                for (int i = 0; i < 4; i++)
                    wmma::mma_sync(acc[i][j], af[i], bf, acc[i][j]);
            }
        }
        __syncthreads();
    }

    // epilogue: stage fp32 accumulators to smem
#pragma unroll
    for (int i = 0; i < 4; i++)
#pragma unroll
        for (int j = 0; j < 2; j++)
            wmma::store_matrix_sync(Csm + (size_t)(wm * 64 + i * 16) * 132 + wn * 32 + j * 16,
                                    acc[i][j], 132, wmma::mem_row_major);
    __syncthreads();

    // logits: thread t -> row r = t&127, local head hh = t>>7
    {
        int r = tid & 127, hh = tid >> 7;
        int head = blockIdx.y * 2 + hh;
        int gr = r0 + r;
        const float* cr = Csm + (size_t)r * 132 + hh * 64;
        const float* av = a_src + head * 64;
        const float* dv = a_dst + head * 64;
        float ps = 0.f, pd = 0.f;
#pragma unroll 8
        for (int c = 0; c < 64; c++) {
            float v = cr[c];
            ps = fmaf(v, __ldg(&av[c]), ps);
            pd = fmaf(v, __ldg(&dv[c]), pd);
        }
        if (gr < NN) {
            g_asrc[gr * NH + head] = ps;
            g_adst[gr * NH + head] = pd;
        }
    }

    // fp16 xh store: thread t -> row r = t>>1, half = t&1 (64 cols)
    {
        int r = tid >> 1, half = tid & 1;
        int gr = r0 + r;
        if (gr < NN) {
            const float* cr = Csm + (size_t)r * 132 + half * 64;
            __half* dr = &g_xh[(size_t)gr * HC + c0 + half * 64];
#pragma unroll
            for (int b = 0; b < 8; b++) {
                float4 f0 = *(const float4*)&cr[b * 8];
                float4 f1 = *(const float4*)&cr[b * 8 + 4];
                h8 u;
                u.a = __floats2half2_rn(f0.x, f0.y);
                u.b = __floats2half2_rn(f0.z, f0.w);
                u.c = __floats2half2_rn(f1.x, f1.y);
                u.d = __floats2half2_rn(f1.z, f1.w);
                ((h8*)dr)[b] = u;
            }
        }
    }
}

__device__ __forceinline__ float lrelu(float v) { return v >= 0.f ? v : 0.2f * v; }

// ---------------- fused logits + softmax + aggregation ---------------------
// outp != nullptr  -> fp32 store (final h). outp == nullptr -> fp16 g_h16.
__global__ void __launch_bounds__(256)
k_agg(const float* __restrict__ bias, int ce_off,
      float* __restrict__ wout, float* __restrict__ outp) {
    __shared__ float s_c[8][128];
    __shared__ int   s_s[8][32];
    int wrp = threadIdx.x >> 5;
    int n = blockIdx.x * 8 + wrp;
    int lane = threadIdx.x & 31;
    if (n >= NN) return;
    int r0 = g_rowstart[n], r1 = g_rowstart[n + 1];
    int deg = r1 - r0;
    int nchunk = (deg + 31) >> 5;
    float4 ad = *(const float4*)&g_adst[n * 4];
    float ce0 = g_ce[ce_off + 0], ce1 = g_ce[ce_off + 1];
    float ce2 = g_ce[ce_off + 2], ce3 = g_ce[ce_off + 3];

    // ---- phase 1: inline logits + online (max, expsum) ----
    float4 ra[3];
    int    rs[3], ro[3];
    float  rat[3];
    float m0 = NEGINF, m1 = NEGINF, m2 = NEGINF, m3 = NEGINF;
    float s0 = 0.f, s1 = 0.f, s2 = 0.f, s3 = 0.f;

#pragma unroll
    for (int c = 0; c < 3; c++) {
        ra[c] = make_float4(NEGINF, NEGINF, NEGINF, NEGINF);
        rs[c] = 0; ro[c] = 0; rat[c] = 0.f;
        if (c < nchunk) {
            int j = r0 + c * 32 + lane;
            if (j < r1) {
                int s = g_esrc_s[j];
                int orig = g_eid_s[j];
                float2 ea2 = g_ea_s[j];
                float4 as4 = *(const float4*)&g_asrc[s * 4];
                float4 a;
                a.x = lrelu(as4.x + ea2.x * ce0 + ad.x);
                a.y = lrelu(as4.y + ea2.x * ce1 + ad.y);
                a.z = lrelu(as4.z + ea2.x * ce2 + ad.z);
                a.w = lrelu(as4.w + ea2.x * ce3 + ad.w);
                ra[c] = a; rs[c] = s; ro[c] = orig; rat[c] = ea2.y;
                float t;
                t = fmaxf(m0, a.x); s0 = s0 * __expf(m0 - t) + __expf(a.x - t); m0 = t;
                t = fmaxf(m1, a.y); s1 = s1 * __expf(m1 - t) + __expf(a.y - t); m1 = t;
                t = fmaxf(m2, a.z); s2 = s2 * __expf(m2 - t) + __expf(a.z - t); m2 = t;
                t = fmaxf(m3, a.w); s3 = s3 * __expf(m3 - t) + __expf(a.w - t); m3 = t;
            }
        }
    }
    for (int c = 3; c < nchunk; c++) {          // rare spill path (deg > 96)
        int j = r0 + c * 32 + lane;
        if (j < r1) {
            int s = g_esrc_s[j];
            float2 ea2 = g_ea_s[j];
            float4 as4 = *(const float4*)&g_asrc[s * 4];
            float4 a;
            a.x = lrelu(as4.x + ea2.x * ce0 + ad.x);
            a.y = lrelu(as4.y + ea2.x * ce1 + ad.y);
            a.z = lrelu(as4.z + ea2.x * ce2 + ad.z);
            a.w = lrelu(as4.w + ea2.x * ce3 + ad.w);
            *(float4*)&g_alpha_s[(size_t)j * 4] = a;
            float t;
            t = fmaxf(m0, a.x); s0 = s0 * __expf(m0 - t) + __expf(a.x - t); m0 = t;
            t = fmaxf(m1, a.y); s1 = s1 * __expf(m1 - t) + __expf(a.y - t); m1 = t;
            t = fmaxf(m2, a.z); s2 = s2 * __expf(m2 - t) + __expf(a.z - t); m2 = t;
            t = fmaxf(m3, a.w); s3 = s3 * __expf(m3 - t) + __expf(a.w - t); m3 = t;
        }
    }
#pragma unroll
    for (int o = 16; o; o >>= 1) {
        float om, os, nm;
        om = __shfl_xor_sync(FULLM, m0, o); os = __shfl_xor_sync(FULLM, s0, o);
        nm = fmaxf(m0, om); s0 = s0 * __expf(m0 - nm) + os * __expf(om - nm); m0 = nm;
        om = __shfl_xor_sync(FULLM, m1, o); os = __shfl_xor_sync(FULLM, s1, o);
        nm = fmaxf(m1, om); s1 = s1 * __expf(m1 - nm) + os * __expf(om - nm); m1 = nm;
        om = __shfl_xor_sync(FULLM, m2, o); os = __shfl_xor_sync(FULLM, s2, o);
        nm = fmaxf(m2, om); s2 = s2 * __expf(m2 - nm) + os * __expf(om - nm); m2 = nm;
        om = __shfl_xor_sync(FULLM, m3, o); os = __shfl_xor_sync(FULLM, s3, o);
        nm = fmaxf(m3, om); s3 = s3 * __expf(m3 - nm) + os * __expf(om - nm); m3 = nm;
    }
    float i0 = 1.f / (s0 + 1e-16f), i1 = 1.f / (s1 + 1e-16f);
    float i2 = 1.f / (s2 + 1e-16f), i3 = 1.f / (s3 + 1e-16f);

    // ---- phase 2: wout scatter + fp16 gather-accumulate ----
    float acc0 = 0.f, acc1 = 0.f, acc2 = 0.f, acc3 = 0.f;
    float acc4 = 0.f, acc5 = 0.f, acc6 = 0.f, acc7 = 0.f;
    int h = lane >> 3;
    int c0 = lane * 8;

    for (int c = 0; c < nchunk; c++) {
        int base = r0 + c * 32;
        int j = base + lane;
        bool valid = j < r1;
        int cnt = min(32, r1 - base);
        float4 a; int s; float at; int orig;
        if (c < 3) {
            a = ra[c]; s = rs[c]; at = rat[c]; orig = ro[c];
        } else {
            s = valid ? g_esrc_s[j] : 0;
            orig = valid ? g_eid_s[j] : 0;
            float2 ea2 = valid ? g_ea_s[j] : make_float2(0.f, 0.f);
            a = valid ? *(const float4*)&g_alpha_s[(size_t)j * 4]
                      : make_float4(NEGINF, NEGINF, NEGINF, NEGINF);
            at = ea2.y;
        }
        float w0 = __expf(a.x - m0) * i0;
        float w1 = __expf(a.y - m1) * i1;
        float w2 = __expf(a.z - m2) * i2;
        float w3 = __expf(a.w - m3) * i3;
        if (valid)
            *(float4*)&wout[(size_t)orig * 4] = make_float4(w0, w1, w2, w3);
        __syncwarp();
        *(float4*)&s_c[wrp][lane * 4] = make_float4(w0 * at, w1 * at, w2 * at, w3 * at);
        s_s[wrp][lane] = s;
        __syncwarp();
        for (int k = 0; k < cnt; k++) {
            float coef = s_c[wrp][k * 4 + h];
            int ss = s_s[wrp][k];
            h8 v = *(const h8*)&g_xh[(size_t)ss * HC + c0];
            float2 f0 = __half22float2(v.a);
            float2 f1 = __half22float2(v.b);
            float2 f2 = __half22float2(v.c);
            float2 f3 = __half22float2(v.d);
            acc0 = fmaf(f0.x, coef, acc0); acc1 = fmaf(f0.y, coef, acc1);
            acc2 = fmaf(f1.x, coef, acc2); acc3 = fmaf(f1.y, coef, acc3);
            acc4 = fmaf(f2.x, coef, acc4); acc5 = fmaf(f2.y, coef, acc5);
            acc6 = fmaf(f3.x, coef, acc6); acc7 = fmaf(f3.y, coef, acc7);
        }
        __syncwarp();
    }

    float4 b0 = *(const float4*)&bias[c0];
    float4 b1 = *(const float4*)&bias[c0 + 4];
    if (outp) {
        float* op = &outp[(size_t)n * HC + c0];
        *(float4*)op = make_float4(acc0 + b0.x, acc1 + b0.y, acc2 + b0.z, acc3 + b0.w);
        *(float4*)(op + 4) = make_float4(acc4 + b1.x, acc5 + b1.y, acc6 + b1.z, acc7 + b1.w);
    } else {
        h8 u;
        u.a = __floats2half2_rn(acc0 + b0.x, acc1 + b0.y);
        u.b = __floats2half2_rn(acc2 + b0.z, acc3 + b0.w);
        u.c = __floats2half2_rn(acc4 + b1.x, acc5 + b1.y);
        u.d = __floats2half2_rn(acc6 + b1.z, acc7 + b1.w);
        *(h8*)&g_h16[(size_t)n * HC + c0] = u;
    }
}

// ---------------- launch ---------------------------------------------------
extern "C" void kernel_launch(void* const* d_in, const int* in_sizes, int n_in,
                              void* d_out, int out_size) {
    const float* x       = (const float*)d_in[0];
    const int*   ei      = (const int*)d_in[1];
    const int*   src     = ei;
    const int*   dst     = ei + NE;
    const float* eattr   = (const float*)d_in[3];
    const float* eatten  = (const float*)d_in[4];
    const float* W1      = (const float*)d_in[5];
    const float* a_src1  = (const float*)d_in[6];
    const float* a_dst1  = (const float*)d_in[7];
    const float* W_e1    = (const float*)d_in[8];
    const float* a_e1    = (const float*)d_in[9];
    const float* b1      = (const float*)d_in[10];
    const float* W2      = (const float*)d_in[11];
    const float* a_src2  = (const float*)d_in[12];
    const float* a_dst2  = (const float*)d_in[13];
    const float* W_e2    = (const float*)d_in[14];
    const float* a_e2    = (const float*)d_in[15];
    const float* b2      = (const float*)d_in[16];

    float* out    = (float*)d_out;
    float* h_out  = out;                        // [NN, 256]
    float* w1_out = out + (size_t)NN * HC;      // [NE, 4]
    float* w2_out = w1_out + (size_t)NE * NH;   // [NE, 4]

    const int EB = (NE + 255) / 256;            // 2500
    const int NB = (NN + 255) / 256;            // 79
    const int AB = NN / 8;                      // 2500
    dim3 gemm_grid((NN + 127) / 128, NH);
    dim3 mma_grid((NN + 127) / 128, 2);
    const int MMA_SMEM = 128 * 132 * 4;         // 67584 B

    cudaFuncSetAttribute(k_mma2, cudaFuncAttributeMaxDynamicSharedMemorySize, MMA_SMEM);

    k_ce<<<1, 256>>>(W_e1, a_e1, W_e2, a_e2);
    k_cvtw<<<(HC * HC / 4) / 256, 256>>>(W2);

    // ---- CSR build (shared by both layers) ----
    k_zero_deg<<<NB, 256>>>();
    k_hist<<<EB, 256>>>(dst);
    k_scanA<<<NSB, 256>>>();
    k_scanB<<<1, 128>>>();
    k_scanC<<<NSB, 256>>>();
    k_scatter<<<EB, 256>>>(src, dst, eattr, eatten);

    // ---- layer 1 (fp32 GEMM, exact logits) ----
    k_gemm<<<gemm_grid, 128>>>(x, W1, a_src1, a_dst1, 128);
    k_agg<<<AB, 256>>>(b1, 0, w1_out, nullptr);     // -> g_h16 (fp16)

    // ---- layer 2 (HMMA GEMM) ----
    k_mma2<<<mma_grid, 256, MMA_SMEM>>>(a_src2, a_dst2);
    k_agg<<<AB, 256>>>(b2, 4, w2_out, h_out);
}